// round 9
// baseline (speedup 1.0000x reference)
#include <cuda_runtime.h>
#include <cuda_bf16.h>

// SparseSelfAttention via portable mma.sync bf16 (3-GEMM emulated fp32), FA2-style.
// R9: pre-pass converts the 256 shared global K/V rows per (b,h) to bf16 hi/lo once;
// main kernel cp.async-double-buffers global chunks (no cvt in hot loop).

#define BSZ    2
#define HEADS  16
#define SEQ    4096
#define DIM    64
#define NCHUNK 5
#define CSHIFT 20.0f
#define NTHREADS 128

#define RS 144                  // smem row stride in BYTES (64 bf16 = 128B + 16B pad)
#define TILE (64 * RS)          // 9216 B per bf16 tile
#define BUFSZ (4 * TILE)        // KH,KL,VH,VL = 36864 B per chunk buffer

// smem map: [buf0 36864][buf1 36864][m01 2x64 floats]
// Q staging tiles alias buf1's VH/VL region (dead after prologue ldmatrix).
#define SM_M01   (2 * BUFSZ)               // 73728
#define SM_TOTAL (SM_M01 + 512)            // 74240 B -> 3 CTAs/SM

typedef unsigned int u32;

// pre-pass scratch: [bh][KH,KL,VH,VL][256 g][64 d] bf16 = 4 MB
__device__ __nv_bfloat16 g_split[32][4][256][64];

static __device__ __forceinline__ u32 smem_u32(const void* p) {
    u32 a;
    asm("{ .reg .u64 t; cvta.to.shared.u64 t, %1; cvt.u32.u64 %0, t; }" : "=r"(a) : "l"(p));
    return a;
}
// pack two floats -> bf16x2 {lo=a, hi=b}
static __device__ __forceinline__ u32 pkbf(float a, float b) {
    u32 r;
    asm("cvt.rn.bf16x2.f32 %0, %1, %2;" : "=r"(r) : "f"(b), "f"(a));
    return r;
}
static __device__ __forceinline__ float lo_f(u32 h) { return __uint_as_float(h << 16); }
static __device__ __forceinline__ float hi_f(u32 h) { return __uint_as_float(h & 0xFFFF0000u); }

static __device__ __forceinline__ void ldsm4(u32& r0, u32& r1, u32& r2, u32& r3, u32 a) {
    asm volatile("ldmatrix.sync.aligned.m8n8.x4.shared.b16 {%0,%1,%2,%3}, [%4];"
                 : "=r"(r0), "=r"(r1), "=r"(r2), "=r"(r3) : "r"(a));
}
static __device__ __forceinline__ void ldsm4t(u32& r0, u32& r1, u32& r2, u32& r3, u32 a) {
    asm volatile("ldmatrix.sync.aligned.m8n8.x4.trans.shared.b16 {%0,%1,%2,%3}, [%4];"
                 : "=r"(r0), "=r"(r1), "=r"(r2), "=r"(r3) : "r"(a));
}
static __device__ __forceinline__ void mma16816(float* c, u32 a0, u32 a1, u32 a2, u32 a3,
                                                u32 b0, u32 b1) {
    asm volatile(
        "mma.sync.aligned.m16n8k16.row.col.f32.bf16.bf16.f32 "
        "{%0,%1,%2,%3}, {%4,%5,%6,%7}, {%8,%9}, {%0,%1,%2,%3};"
        : "+f"(c[0]), "+f"(c[1]), "+f"(c[2]), "+f"(c[3])
        : "r"(a0), "r"(a1), "r"(a2), "r"(a3), "r"(b0), "r"(b1));
}
static __device__ __forceinline__ void cpasync16(u32 dst, const void* src) {
    asm volatile("cp.async.cg.shared.global [%0], [%1], 16;" :: "r"(dst), "l"(src));
}
#define CP_COMMIT() asm volatile("cp.async.commit_group;" ::: "memory")

// global key index g -> sequence position
static __device__ __forceinline__ int gpos(int g) {
    int blk = g >> 2, off = g & 3;
    return blk * 64 + (off == 0 ? 0 : 60 + off);
}

// ================= pre-pass: gather + split global K/V rows =================
__global__ __launch_bounds__(256)
void prepass_kernel(const float* __restrict__ K, const float* __restrict__ V)
{
    const int bh  = blockIdx.y;                        // 0..31
    const int tid = threadIdx.x + blockIdx.x * 256;    // 0..2047
    const size_t bh_off = (size_t)bh * SEQ * DIM;
    uint2* out = (uint2*)g_split;                      // 4 bf16 per uint2

    #pragma unroll
    for (int i = 0; i < 2; i++) {
        int idx = tid + i * 2048;                      // 0..4095: g = idx>>4, d4 = idx&15
        int g = idx >> 4, d4 = idx & 15;
        int pos = gpos(g);

        float4 kf = *(const float4*)(K + bh_off + (size_t)pos * DIM + d4 * 4);
        u32 h01 = pkbf(kf.x, kf.y), h23 = pkbf(kf.z, kf.w);
        u32 l01 = pkbf(kf.x - lo_f(h01), kf.y - hi_f(h01));
        u32 l23 = pkbf(kf.z - lo_f(h23), kf.w - hi_f(h23));
        out[(bh * 4 + 0) * 4096 + g * 16 + d4] = make_uint2(h01, h23);
        out[(bh * 4 + 1) * 4096 + g * 16 + d4] = make_uint2(l01, l23);

        float4 vf = *(const float4*)(V + bh_off + (size_t)pos * DIM + d4 * 4);
        u32 vh01 = pkbf(vf.x, vf.y), vh23 = pkbf(vf.z, vf.w);
        u32 vl01 = pkbf(vf.x - lo_f(vh01), vf.y - hi_f(vh01));
        u32 vl23 = pkbf(vf.z - lo_f(vh23), vf.w - hi_f(vh23));
        out[(bh * 4 + 2) * 4096 + g * 16 + d4] = make_uint2(vh01, vh23);
        out[(bh * 4 + 3) * 4096 + g * 16 + d4] = make_uint2(vl01, vl23);
    }
}

// ================= main kernel =================
extern __shared__ char smc[];

__global__ __launch_bounds__(NTHREADS)
void sparse_attn_mma(const float* __restrict__ Q,
                     const float* __restrict__ K,
                     const float* __restrict__ V,
                     const float* __restrict__ Mask,
                     float* __restrict__ Out)
{
    const int qb = blockIdx.x;
    const int h  = blockIdx.y;
    const int b  = blockIdx.z;
    const int bh = b * HEADS + h;
    const size_t bh_off = (size_t)bh * SEQ * DIM;
    const size_t q_off  = bh_off + (size_t)qb * 64 * DIM;

    const int tid  = threadIdx.x;
    const int L    = tid & 31;
    const int warp = tid >> 5;          // 0..3
    const int qw   = warp * 16;         // warp's first query row

    const u32 smb = smem_u32(smc);
    float* s_m01 = (float*)(smc + SM_M01);      // [2][64]
    const u32 QH = smb + BUFSZ + 2 * TILE;      // alias of buf1.VH
    const u32 QL = QH + TILE;                   // alias of buf1.VL

    // ---- prologue: stage Q -> QH/QL, local chunk0 K/V -> buf0, mask0 ----
    #pragma unroll
    for (int i = 0; i < 8; i++) {
        int idx = tid + i * NTHREADS;           // 0..1023 float4s
        int row = idx >> 4, d4 = idx & 15;
        float4 f = *(const float4*)(Q + q_off + (size_t)row * DIM + d4 * 4);
        u32 h01 = pkbf(f.x, f.y), h23 = pkbf(f.z, f.w);
        u32 l01 = pkbf(f.x - lo_f(h01), f.y - hi_f(h01));
        u32 l23 = pkbf(f.z - lo_f(h23), f.w - hi_f(h23));
        *(uint2*)(smc + (QH - smb) + row * RS + d4 * 8) = make_uint2(h01, h23);
        *(uint2*)(smc + (QL - smb) + row * RS + d4 * 8) = make_uint2(l01, l23);

        int pos = qb * 64 + row;
        float4 kf = *(const float4*)(K + bh_off + (size_t)pos * DIM + d4 * 4);
        u32 kh01 = pkbf(kf.x, kf.y), kh23 = pkbf(kf.z, kf.w);
        u32 kl01 = pkbf(kf.x - lo_f(kh01), kf.y - hi_f(kh01));
        u32 kl23 = pkbf(kf.z - lo_f(kh23), kf.w - hi_f(kh23));
        *(uint2*)(smc + 0 * TILE + row * RS + d4 * 8) = make_uint2(kh01, kh23);
        *(uint2*)(smc + 1 * TILE + row * RS + d4 * 8) = make_uint2(kl01, kl23);

        float4 vf = *(const float4*)(V + bh_off + (size_t)pos * DIM + d4 * 4);
        u32 vh01 = pkbf(vf.x, vf.y), vh23 = pkbf(vf.z, vf.w);
        u32 vl01 = pkbf(vf.x - lo_f(vh01), vf.y - hi_f(vh01));
        u32 vl23 = pkbf(vf.z - lo_f(vh23), vf.w - hi_f(vh23));
        *(uint2*)(smc + 2 * TILE + row * RS + d4 * 8) = make_uint2(vh01, vh23);
        *(uint2*)(smc + 3 * TILE + row * RS + d4 * 8) = make_uint2(vl01, vl23);
    }
    if (tid < 64)
        s_m01[tid] = (Mask[b * SEQ + qb * 64 + tid] == 0.0f) ? 0.0f : 1.0f;
    __syncthreads();

    // ---- persistent Q A-fragments (4 k-tiles, hi+lo) ----
    u32 qh[4][4], ql[4][4];
    {
        int r    = L & 7;
        int rofs = ((L >> 3) & 1) * 8;
        int cofs = ((L >> 4) & 1) * 16;
        #pragma unroll
        for (int kt = 0; kt < 4; kt++) {
            u32 a = (qw + r + rofs) * RS + kt * 32 + cofs;
            ldsm4(qh[kt][0], qh[kt][1], qh[kt][2], qh[kt][3], QH + a);
            ldsm4(ql[kt][0], ql[kt][1], ql[kt][2], ql[kt][3], QL + a);
        }
    }
    __syncthreads();   // all warps done reading Q tiles (buf1.V area now free)

    const char* gsrc = (const char*)g_split + (size_t)bh * 4 * 32768;

    // issue chunk1 -> buf1 (+ mask1)
    {
        u32 bufb = smb + BUFSZ;
        #pragma unroll
        for (int t = 0; t < 4; t++)
            #pragma unroll
            for (int kk = 0; kk < 4; kk++) {
                int seg = tid + kk * NTHREADS;      // 0..511
                int row = seg >> 3, c16 = seg & 7;
                cpasync16(bufb + t * TILE + row * RS + c16 * 16,
                          gsrc + t * 32768 + row * 128 + c16 * 16);
            }
        if (tid < 64)
            s_m01[64 + tid] = (Mask[b * SEQ + gpos(tid)] == 0.0f) ? 0.0f : 1.0f;
        CP_COMMIT();
    }

    float O[8][4];
    #pragma unroll
    for (int nt = 0; nt < 8; nt++)
        #pragma unroll
        for (int e = 0; e < 4; e++) O[nt][e] = 0.0f;
    float rs0 = 0.0f, rs1 = 0.0f;

    for (int c = 0; c < NCHUNK; c++) {
        if (c == 4)      asm volatile("cp.async.wait_group 0;" ::: "memory");
        else if (c >= 1) asm volatile("cp.async.wait_group 1;" ::: "memory");
        __syncthreads();                       // chunk c data visible to all

        const u32 bufb = smb + (c & 1) * BUFSZ;
        const u32 aKH = bufb, aKL = bufb + TILE, aVH = bufb + 2 * TILE, aVL = bufb + 3 * TILE;
        const float* m01 = s_m01 + (c & 1) * 64;

        // ---- QK: C = Qh*Kh + Qh*Kl + Ql*Kh ----
        float C[8][4];
        #pragma unroll
        for (int nt = 0; nt < 8; nt++)
            #pragma unroll
            for (int e = 0; e < 4; e++) C[nt][e] = 0.0f;
        {
            int r    = L & 7;
            int rofs = ((L >> 4) & 1) * 8;
            int cofs = ((L >> 3) & 1) * 16;
            #pragma unroll
            for (int kt = 0; kt < 4; kt++)
                #pragma unroll
                for (int np = 0; np < 4; np++) {
                    u32 a = (np * 16 + r + rofs) * RS + kt * 32 + cofs;
                    u32 b0, b1, b2, b3;
                    ldsm4(b0, b1, b2, b3, aKH + a);
                    mma16816(C[2 * np],     qh[kt][0], qh[kt][1], qh[kt][2], qh[kt][3], b0, b1);
                    mma16816(C[2 * np + 1], qh[kt][0], qh[kt][1], qh[kt][2], qh[kt][3], b2, b3);
                    mma16816(C[2 * np],     ql[kt][0], ql[kt][1], ql[kt][2], ql[kt][3], b0, b1);
                    mma16816(C[2 * np + 1], ql[kt][0], ql[kt][1], ql[kt][2], ql[kt][3], b2, b3);
                    ldsm4(b0, b1, b2, b3, aKL + a);
                    mma16816(C[2 * np],     qh[kt][0], qh[kt][1], qh[kt][2], qh[kt][3], b0, b1);
                    mma16816(C[2 * np + 1], qh[kt][0], qh[kt][1], qh[kt][2], qh[kt][3], b2, b3);
                }
        }

        // ---- exp + mask + row-sum + split into P hi/lo A-fragments ----
        u32 ph[4][4], pl[4][4];
        #pragma unroll
        for (int nt = 0; nt < 8; nt++) {
            float2 mm = *(const float2*)(m01 + nt * 8 + 2 * (L & 3));
            float p0 = __expf(C[nt][0] - CSHIFT) * mm.x;
            float p1 = __expf(C[nt][1] - CSHIFT) * mm.y;
            float p2 = __expf(C[nt][2] - CSHIFT) * mm.x;
            float p3 = __expf(C[nt][3] - CSHIFT) * mm.y;
            rs0 += p0 + p1;
            rs1 += p2 + p3;
            u32 hA = pkbf(p0, p1), hB = pkbf(p2, p3);
            u32 lA = pkbf(p0 - lo_f(hA), p1 - hi_f(hA));
            u32 lB = pkbf(p2 - lo_f(hB), p3 - hi_f(hB));
            int kt = nt >> 1, e = (nt & 1) * 2;
            ph[kt][e] = hA; ph[kt][e + 1] = hB;
            pl[kt][e] = lA; pl[kt][e + 1] = lB;
        }

        // ---- PV: O += Ph*Vh + Ph*Vl + Pl*Vh ----
        {
            int r    = L & 7;
            int rofs = ((L >> 3) & 1) * 8;
            int cofs = ((L >> 4) & 1) * 16;
            #pragma unroll
            for (int kt = 0; kt < 4; kt++)
                #pragma unroll
                for (int np = 0; np < 4; np++) {
                    u32 a = (kt * 16 + r + rofs) * RS + np * 32 + cofs;
                    u32 b0, b1, b2, b3;
                    ldsm4t(b0, b1, b2, b3, aVH + a);
                    mma16816(O[2 * np],     ph[kt][0], ph[kt][1], ph[kt][2], ph[kt][3], b0, b1);
                    mma16816(O[2 * np + 1], ph[kt][0], ph[kt][1], ph[kt][2], ph[kt][3], b2, b3);
                    mma16816(O[2 * np],     pl[kt][0], pl[kt][1], pl[kt][2], pl[kt][3], b0, b1);
                    mma16816(O[2 * np + 1], pl[kt][0], pl[kt][1], pl[kt][2], pl[kt][3], b2, b3);
                    ldsm4t(b0, b1, b2, b3, aVL + a);
                    mma16816(O[2 * np],     ph[kt][0], ph[kt][1], ph[kt][2], ph[kt][3], b0, b1);
                    mma16816(O[2 * np + 1], ph[kt][0], ph[kt][1], ph[kt][2], ph[kt][3], b2, b3);
                }
        }

        __syncthreads();                       // all readers done with buf[c&1]

        // ---- prefetch chunk c+2 -> buf[c&1] ----
        if (c + 2 <= 4) {
            int cc = c + 2;
            u32 bufb2 = smb + (cc & 1) * BUFSZ;
            int g0 = (cc - 1) * 64;
            #pragma unroll
            for (int t = 0; t < 4; t++)
                #pragma unroll
                for (int kk = 0; kk < 4; kk++) {
                    int seg = tid + kk * NTHREADS;
                    int row = seg >> 3, c16 = seg & 7;
                    cpasync16(bufb2 + t * TILE + row * RS + c16 * 16,
                              gsrc + t * 32768 + (g0 + row) * 128 + c16 * 16);
                }
            if (tid < 64)
                s_m01[(cc & 1) * 64 + tid] =
                    (Mask[b * SEQ + gpos(g0 + tid)] == 0.0f) ? 0.0f : 1.0f;
            CP_COMMIT();
        }
    }

    // ---- reduce row sums over the 4 lanes sharing each row, normalize, store ----
    rs0 += __shfl_xor_sync(0xffffffffu, rs0, 1);
    rs0 += __shfl_xor_sync(0xffffffffu, rs0, 2);
    rs1 += __shfl_xor_sync(0xffffffffu, rs1, 1);
    rs1 += __shfl_xor_sync(0xffffffffu, rs1, 2);
    float inv0 = 1.0f / rs0;
    float inv1 = 1.0f / rs1;

    {
        int row0 = qw + (L >> 2);
        int col  = 2 * (L & 3);
        float* o0 = Out + q_off + (size_t)row0 * DIM + col;
        float* o1 = o0 + 8 * DIM;
        #pragma unroll
        for (int nt = 0; nt < 8; nt++) {
            *(float2*)(o0 + nt * 8) = make_float2(O[nt][0] * inv0, O[nt][1] * inv0);
            *(float2*)(o1 + nt * 8) = make_float2(O[nt][2] * inv1, O[nt][3] * inv1);
        }
    }
}

extern "C" void kernel_launch(void* const* d_in, const int* in_sizes, int n_in,
                              void* d_out, int out_size)
{
    const float* Q = (const float*)d_in[0];
    const float* K = (const float*)d_in[1];
    const float* V = (const float*)d_in[2];
    const float* M = (const float*)d_in[3];
    float* O = (float*)d_out;

    dim3 pgrid(8, 32);
    prepass_kernel<<<pgrid, 256>>>(K, V);

    cudaFuncSetAttribute(sparse_attn_mma,
                         cudaFuncAttributeMaxDynamicSharedMemorySize, SM_TOTAL);
    dim3 grid(SEQ / 64, HEADS, BSZ);    // (64, 16, 2)
    sparse_attn_mma<<<grid, NTHREADS, SM_TOTAL>>>(Q, K, V, M, O);
}

// round 10
// speedup vs baseline: 1.1139x; 1.1139x over previous
#include <cuda_runtime.h>
#include <cuda_bf16.h>

// SparseSelfAttention via portable mma.sync bf16 (3-GEMM emulated fp32), FA2-style.
// R10: ldsm double-buffer prefetch in QK/PV loops, reg cap 170 (3 CTAs),
// log2e folded into K so epilogue is raw ex2.approx.

#define BSZ    2
#define HEADS  16
#define SEQ    4096
#define DIM    64
#define NCHUNK 5
#define SHIFT2 28.853900817779268f   // 20 * log2(e)
#define LOG2E  1.4426950408889634f
#define NTHREADS 128

#define RS 144                  // smem row stride in BYTES (64 bf16 = 128B + 16B pad)
#define TILE (64 * RS)          // 9216 B per bf16 tile
#define BUFSZ (4 * TILE)        // KH,KL,VH,VL = 36864 B per chunk buffer

// smem map: [buf0 36864][buf1 36864][m01 2x64 floats]
// Q staging tiles alias buf1's VH/VL region (dead after prologue ldmatrix).
#define SM_M01   (2 * BUFSZ)               // 73728
#define SM_TOTAL (SM_M01 + 512)            // 74240 B -> 3 CTAs/SM

typedef unsigned int u32;

// pre-pass scratch: [bh][KH,KL,VH,VL][256 g][64 d] bf16 = 4 MB (K pre-scaled by log2e)
__device__ __nv_bfloat16 g_split[32][4][256][64];

static __device__ __forceinline__ u32 smem_u32(const void* p) {
    u32 a;
    asm("{ .reg .u64 t; cvta.to.shared.u64 t, %1; cvt.u32.u64 %0, t; }" : "=r"(a) : "l"(p));
    return a;
}
// pack two floats -> bf16x2 {lo=a, hi=b}
static __device__ __forceinline__ u32 pkbf(float a, float b) {
    u32 r;
    asm("cvt.rn.bf16x2.f32 %0, %1, %2;" : "=r"(r) : "f"(b), "f"(a));
    return r;
}
static __device__ __forceinline__ float lo_f(u32 h) { return __uint_as_float(h << 16); }
static __device__ __forceinline__ float hi_f(u32 h) { return __uint_as_float(h & 0xFFFF0000u); }
static __device__ __forceinline__ float ex2(float x) {
    float y;
    asm("ex2.approx.f32 %0, %1;" : "=f"(y) : "f"(x));
    return y;
}

static __device__ __forceinline__ void ldsm4(u32* r, u32 a) {
    asm volatile("ldmatrix.sync.aligned.m8n8.x4.shared.b16 {%0,%1,%2,%3}, [%4];"
                 : "=r"(r[0]), "=r"(r[1]), "=r"(r[2]), "=r"(r[3]) : "r"(a));
}
static __device__ __forceinline__ void ldsm4t(u32* r, u32 a) {
    asm volatile("ldmatrix.sync.aligned.m8n8.x4.trans.shared.b16 {%0,%1,%2,%3}, [%4];"
                 : "=r"(r[0]), "=r"(r[1]), "=r"(r[2]), "=r"(r[3]) : "r"(a));
}
static __device__ __forceinline__ void mma16816(float* c, const u32* a, u32 b0, u32 b1) {
    asm volatile(
        "mma.sync.aligned.m16n8k16.row.col.f32.bf16.bf16.f32 "
        "{%0,%1,%2,%3}, {%4,%5,%6,%7}, {%8,%9}, {%0,%1,%2,%3};"
        : "+f"(c[0]), "+f"(c[1]), "+f"(c[2]), "+f"(c[3])
        : "r"(a[0]), "r"(a[1]), "r"(a[2]), "r"(a[3]), "r"(b0), "r"(b1));
}
static __device__ __forceinline__ void cpasync16(u32 dst, const void* src) {
    asm volatile("cp.async.cg.shared.global [%0], [%1], 16;" :: "r"(dst), "l"(src));
}
#define CP_COMMIT() asm volatile("cp.async.commit_group;" ::: "memory")

// global key index g -> sequence position
static __device__ __forceinline__ int gpos(int g) {
    int blk = g >> 2, off = g & 3;
    return blk * 64 + (off == 0 ? 0 : 60 + off);
}

// ================= pre-pass: gather + split global K/V rows (K scaled by log2e) ====
__global__ __launch_bounds__(256)
void prepass_kernel(const float* __restrict__ K, const float* __restrict__ V)
{
    const int bh  = blockIdx.y;                        // 0..31
    const int tid = threadIdx.x + blockIdx.x * 256;    // 0..2047
    const size_t bh_off = (size_t)bh * SEQ * DIM;
    uint2* out = (uint2*)g_split;                      // 4 bf16 per uint2

    #pragma unroll
    for (int i = 0; i < 2; i++) {
        int idx = tid + i * 2048;                      // 0..4095: g = idx>>4, d4 = idx&15
        int g = idx >> 4, d4 = idx & 15;
        int pos = gpos(g);

        float4 kf = *(const float4*)(K + bh_off + (size_t)pos * DIM + d4 * 4);
        kf.x *= LOG2E; kf.y *= LOG2E; kf.z *= LOG2E; kf.w *= LOG2E;
        u32 h01 = pkbf(kf.x, kf.y), h23 = pkbf(kf.z, kf.w);
        u32 l01 = pkbf(kf.x - lo_f(h01), kf.y - hi_f(h01));
        u32 l23 = pkbf(kf.z - lo_f(h23), kf.w - hi_f(h23));
        out[(bh * 4 + 0) * 4096 + g * 16 + d4] = make_uint2(h01, h23);
        out[(bh * 4 + 1) * 4096 + g * 16 + d4] = make_uint2(l01, l23);

        float4 vf = *(const float4*)(V + bh_off + (size_t)pos * DIM + d4 * 4);
        u32 vh01 = pkbf(vf.x, vf.y), vh23 = pkbf(vf.z, vf.w);
        u32 vl01 = pkbf(vf.x - lo_f(vh01), vf.y - hi_f(vh01));
        u32 vl23 = pkbf(vf.z - lo_f(vh23), vf.w - hi_f(vh23));
        out[(bh * 4 + 2) * 4096 + g * 16 + d4] = make_uint2(vh01, vh23);
        out[(bh * 4 + 3) * 4096 + g * 16 + d4] = make_uint2(vl01, vl23);
    }
}

// ================= main kernel =================
extern __shared__ char smc[];

__global__ __launch_bounds__(NTHREADS, 3)
void sparse_attn_mma(const float* __restrict__ Q,
                     const float* __restrict__ K,
                     const float* __restrict__ V,
                     const float* __restrict__ Mask,
                     float* __restrict__ Out)
{
    const int qb = blockIdx.x;
    const int h  = blockIdx.y;
    const int b  = blockIdx.z;
    const int bh = b * HEADS + h;
    const size_t bh_off = (size_t)bh * SEQ * DIM;
    const size_t q_off  = bh_off + (size_t)qb * 64 * DIM;

    const int tid  = threadIdx.x;
    const int L    = tid & 31;
    const int warp = tid >> 5;          // 0..3
    const int qw   = warp * 16;         // warp's first query row

    const u32 smb = smem_u32(smc);
    float* s_m01 = (float*)(smc + SM_M01);      // [2][64]
    const u32 QH = smb + BUFSZ + 2 * TILE;      // alias of buf1.VH
    const u32 QL = QH + TILE;                   // alias of buf1.VL

    // ---- prologue: stage Q -> QH/QL, local chunk0 K/V -> buf0, mask0 ----
    #pragma unroll
    for (int i = 0; i < 8; i++) {
        int idx = tid + i * NTHREADS;           // 0..1023 float4s
        int row = idx >> 4, d4 = idx & 15;
        float4 f = *(const float4*)(Q + q_off + (size_t)row * DIM + d4 * 4);
        u32 h01 = pkbf(f.x, f.y), h23 = pkbf(f.z, f.w);
        u32 l01 = pkbf(f.x - lo_f(h01), f.y - hi_f(h01));
        u32 l23 = pkbf(f.z - lo_f(h23), f.w - hi_f(h23));
        *(uint2*)(smc + (QH - smb) + row * RS + d4 * 8) = make_uint2(h01, h23);
        *(uint2*)(smc + (QL - smb) + row * RS + d4 * 8) = make_uint2(l01, l23);

        int pos = qb * 64 + row;
        float4 kf = *(const float4*)(K + bh_off + (size_t)pos * DIM + d4 * 4);
        kf.x *= LOG2E; kf.y *= LOG2E; kf.z *= LOG2E; kf.w *= LOG2E;
        u32 kh01 = pkbf(kf.x, kf.y), kh23 = pkbf(kf.z, kf.w);
        u32 kl01 = pkbf(kf.x - lo_f(kh01), kf.y - hi_f(kh01));
        u32 kl23 = pkbf(kf.z - lo_f(kh23), kf.w - hi_f(kh23));
        *(uint2*)(smc + 0 * TILE + row * RS + d4 * 8) = make_uint2(kh01, kh23);
        *(uint2*)(smc + 1 * TILE + row * RS + d4 * 8) = make_uint2(kl01, kl23);

        float4 vf = *(const float4*)(V + bh_off + (size_t)pos * DIM + d4 * 4);
        u32 vh01 = pkbf(vf.x, vf.y), vh23 = pkbf(vf.z, vf.w);
        u32 vl01 = pkbf(vf.x - lo_f(vh01), vf.y - hi_f(vh01));
        u32 vl23 = pkbf(vf.z - lo_f(vh23), vf.w - hi_f(vh23));
        *(uint2*)(smc + 2 * TILE + row * RS + d4 * 8) = make_uint2(vh01, vh23);
        *(uint2*)(smc + 3 * TILE + row * RS + d4 * 8) = make_uint2(vl01, vl23);
    }
    if (tid < 64)
        s_m01[tid] = (Mask[b * SEQ + qb * 64 + tid] == 0.0f) ? 0.0f : 1.0f;
    __syncthreads();

    // ---- persistent Q A-fragments (4 k-tiles, hi+lo) ----
    u32 qh[4][4], ql[4][4];
    {
        int r    = L & 7;
        int rofs = ((L >> 3) & 1) * 8;
        int cofs = ((L >> 4) & 1) * 16;
        #pragma unroll
        for (int kt = 0; kt < 4; kt++) {
            u32 a = (qw + r + rofs) * RS + kt * 32 + cofs;
            ldsm4(qh[kt], QH + a);
            ldsm4(ql[kt], QL + a);
        }
    }
    __syncthreads();   // all warps done reading Q tiles (buf1.V area now free)

    const char* gsrc = (const char*)g_split + (size_t)bh * 4 * 32768;

    // issue chunk1 -> buf1 (+ mask1)
    {
        u32 bufb = smb + BUFSZ;
        #pragma unroll
        for (int t = 0; t < 4; t++)
            #pragma unroll
            for (int kk = 0; kk < 4; kk++) {
                int seg = tid + kk * NTHREADS;      // 0..511
                int row = seg >> 3, c16 = seg & 7;
                cpasync16(bufb + t * TILE + row * RS + c16 * 16,
                          gsrc + t * 32768 + row * 128 + c16 * 16);
            }
        if (tid < 64)
            s_m01[64 + tid] = (Mask[b * SEQ + gpos(tid)] == 0.0f) ? 0.0f : 1.0f;
        CP_COMMIT();
    }

    float O[8][4];
    #pragma unroll
    for (int nt = 0; nt < 8; nt++)
        #pragma unroll
        for (int e = 0; e < 4; e++) O[nt][e] = 0.0f;
    float rs0 = 0.0f, rs1 = 0.0f;

    for (int c = 0; c < NCHUNK; c++) {
        if (c == 4)      asm volatile("cp.async.wait_group 0;" ::: "memory");
        else if (c >= 1) asm volatile("cp.async.wait_group 1;" ::: "memory");
        __syncthreads();                       // chunk c data visible to all

        const u32 bufb = smb + (c & 1) * BUFSZ;
        const u32 aKH = bufb, aKL = bufb + TILE, aVH = bufb + 2 * TILE, aVL = bufb + 3 * TILE;
        const float* m01 = s_m01 + (c & 1) * 64;

        // ---- QK: C = Qh*Kh + Qh*Kl + Ql*Kh, ldsm double-buffered ----
        float C[8][4];
        #pragma unroll
        for (int nt = 0; nt < 8; nt++)
            #pragma unroll
            for (int e = 0; e < 4; e++) C[nt][e] = 0.0f;
        {
            int r    = L & 7;
            int rofs = ((L >> 4) & 1) * 8;
            int cofs = ((L >> 3) & 1) * 16;
            const u32 abase = (u32)((r + rofs) * RS + cofs);

            u32 BH[2][4], BL[2][4];
            ldsm4(BH[0], aKH + abase);
            ldsm4(BL[0], aKL + abase);
            #pragma unroll
            for (int s = 0; s < 16; s++) {
                int kt = s >> 2, np = s & 3;
                int cur = s & 1, nxt = cur ^ 1;
                if (s < 15) {
                    int s1 = s + 1;
                    u32 a1 = abase + (u32)((s1 & 3) * 16 * RS + (s1 >> 2) * 32);
                    ldsm4(BH[nxt], aKH + a1);
                    ldsm4(BL[nxt], aKL + a1);
                }
                mma16816(C[2 * np],     qh[kt], BH[cur][0], BH[cur][1]);
                mma16816(C[2 * np + 1], qh[kt], BH[cur][2], BH[cur][3]);
                mma16816(C[2 * np],     ql[kt], BH[cur][0], BH[cur][1]);
                mma16816(C[2 * np + 1], ql[kt], BH[cur][2], BH[cur][3]);
                mma16816(C[2 * np],     qh[kt], BL[cur][0], BL[cur][1]);
                mma16816(C[2 * np + 1], qh[kt], BL[cur][2], BL[cur][3]);
            }
        }

        // ---- epilogue: p = ex2(C - SHIFT2) * mask, row-sum, split -> P hi/lo ----
        u32 ph[4][4], pl[4][4];
        #pragma unroll
        for (int nt = 0; nt < 8; nt++) {
            float2 mm = *(const float2*)(m01 + nt * 8 + 2 * (L & 3));
            float p0 = ex2(C[nt][0] - SHIFT2) * mm.x;
            float p1 = ex2(C[nt][1] - SHIFT2) * mm.y;
            float p2 = ex2(C[nt][2] - SHIFT2) * mm.x;
            float p3 = ex2(C[nt][3] - SHIFT2) * mm.y;
            rs0 += p0 + p1;
            rs1 += p2 + p3;
            u32 hA = pkbf(p0, p1), hB = pkbf(p2, p3);
            u32 lA = pkbf(p0 - lo_f(hA), p1 - hi_f(hA));
            u32 lB = pkbf(p2 - lo_f(hB), p3 - hi_f(hB));
            int kt = nt >> 1, e = (nt & 1) * 2;
            ph[kt][e] = hA; ph[kt][e + 1] = hB;
            pl[kt][e] = lA; pl[kt][e + 1] = lB;
        }

        // ---- PV: O += Ph*Vh + Ph*Vl + Pl*Vh, ldsm double-buffered ----
        {
            int r    = L & 7;
            int rofs = ((L >> 3) & 1) * 8;
            int cofs = ((L >> 4) & 1) * 16;
            const u32 abase = (u32)((r + rofs) * RS + cofs);

            u32 BH[2][4], BL[2][4];
            ldsm4t(BH[0], aVH + abase);
            ldsm4t(BL[0], aVL + abase);
            #pragma unroll
            for (int s = 0; s < 16; s++) {
                int kt = s >> 2, np = s & 3;
                int cur = s & 1, nxt = cur ^ 1;
                if (s < 15) {
                    int s1 = s + 1;
                    u32 a1 = abase + (u32)((s1 >> 2) * 16 * RS + (s1 & 3) * 32);
                    ldsm4t(BH[nxt], aVH + a1);
                    ldsm4t(BL[nxt], aVL + a1);
                }
                mma16816(O[2 * np],     ph[kt], BH[cur][0], BH[cur][1]);
                mma16816(O[2 * np + 1], ph[kt], BH[cur][2], BH[cur][3]);
                mma16816(O[2 * np],     pl[kt], BH[cur][0], BH[cur][1]);
                mma16816(O[2 * np + 1], pl[kt], BH[cur][2], BH[cur][3]);
                mma16816(O[2 * np],     ph[kt], BL[cur][0], BL[cur][1]);
                mma16816(O[2 * np + 1], ph[kt], BL[cur][2], BL[cur][3]);
            }
        }

        __syncthreads();                       // all readers done with buf[c&1]

        // ---- prefetch chunk c+2 -> buf[c&1] ----
        if (c + 2 <= 4) {
            int cc = c + 2;
            u32 bufb2 = smb + (cc & 1) * BUFSZ;
            int g0 = (cc - 1) * 64;
            #pragma unroll
            for (int t = 0; t < 4; t++)
                #pragma unroll
                for (int kk = 0; kk < 4; kk++) {
                    int seg = tid + kk * NTHREADS;
                    int row = seg >> 3, c16 = seg & 7;
                    cpasync16(bufb2 + t * TILE + row * RS + c16 * 16,
                              gsrc + t * 32768 + (g0 + row) * 128 + c16 * 16);
                }
            if (tid < 64)
                s_m01[(cc & 1) * 64 + tid] =
                    (Mask[b * SEQ + gpos(g0 + tid)] == 0.0f) ? 0.0f : 1.0f;
            CP_COMMIT();
        }
    }

    // ---- reduce row sums over the 4 lanes sharing each row, normalize, store ----
    rs0 += __shfl_xor_sync(0xffffffffu, rs0, 1);
    rs0 += __shfl_xor_sync(0xffffffffu, rs0, 2);
    rs1 += __shfl_xor_sync(0xffffffffu, rs1, 1);
    rs1 += __shfl_xor_sync(0xffffffffu, rs1, 2);
    float inv0 = 1.0f / rs0;
    float inv1 = 1.0f / rs1;

    {
        int row0 = qw + (L >> 2);
        int col  = 2 * (L & 3);
        float* o0 = Out + q_off + (size_t)row0 * DIM + col;
        float* o1 = o0 + 8 * DIM;
        #pragma unroll
        for (int nt = 0; nt < 8; nt++) {
            *(float2*)(o0 + nt * 8) = make_float2(O[nt][0] * inv0, O[nt][1] * inv0);
            *(float2*)(o1 + nt * 8) = make_float2(O[nt][2] * inv1, O[nt][3] * inv1);
        }
    }
}

extern "C" void kernel_launch(void* const* d_in, const int* in_sizes, int n_in,
                              void* d_out, int out_size)
{
    const float* Q = (const float*)d_in[0];
    const float* K = (const float*)d_in[1];
    const float* V = (const float*)d_in[2];
    const float* M = (const float*)d_in[3];
    float* O = (float*)d_out;

    dim3 pgrid(8, 32);
    prepass_kernel<<<pgrid, 256>>>(K, V);

    cudaFuncSetAttribute(sparse_attn_mma,
                         cudaFuncAttributeMaxDynamicSharedMemorySize, SM_TOTAL);
    dim3 grid(SEQ / 64, HEADS, BSZ);    // (64, 16, 2)
    sparse_attn_mma<<<grid, NTHREADS, SM_TOTAL>>>(Q, K, V, M, O);
}